// round 7
// baseline (speedup 1.0000x reference)
#include <cuda_runtime.h>

// Fixed shapes
#define B_   16
#define J_   1024
#define L_   4096
#define D_   512
#define D4   128          // D/4 float4 lanes
#define NCH  64           // chunks along J
#define CLEN 16           // J per chunk
#define NSG  2            // subgroups per chunk (inside block)
#define SLEN 8            // J per subgroup
#define EPSV 1e-4f

// Scratch (device globals)
__device__ float  g_partialA[B_ * NCH];          // per-chunk total decay product
__device__ float  g_cumA[B_ * J_];               // within-chunk inclusive prod(a)
__device__ float4 g_partialEnd[B_ * NCH * D4];   // per-chunk end state (prev=0), 2 MiB
__device__ float4 g_carry[B_ * NCH * D4];        // state entering each chunk,   2 MiB
__device__ float4 g_smoothed[B_ * J_ * D4];      // chunk-exact scan, 32 MiB
__device__ int    g_idx[B_ * L_];                // gather indices

// ---------------------------------------------------------------------------
// Kernel 1: per-chunk exact EMA from prev=0 via 2 subgroups of 8 steps.
// grid (NCH, B), 256 threads: subgroup g = t>>7, lane d4 = t&127.
// ---------------------------------------------------------------------------
__global__ void __launch_bounds__(256, 5)
k_partial(const float4* __restrict__ emb,
          const float*  __restrict__ conf,
          const int*    __restrict__ mask) {
    const int c = blockIdx.x, b = blockIdx.y, t = threadIdx.x;
    const int g = t >> 7, d4 = t & 127;

    __shared__ float  sa[CLEN], sb[CLEN], sSeg[CLEN];
    __shared__ float4 sEnd[D4];                  // subgroup-0 end state

    if (t < CLEN) {  // lanes 0..15 of warp 0
        const int j = c * CLEN + t;
        float p = conf[b * J_ + j];
        p = fminf(fmaxf(p, EPSV), 1.0f - EPSV);
        const bool m = mask[b * J_ + j] != 0;
        const float a = m ? (1.0f - p) : 1.0f;
        sa[t] = a;
        sb[t] = m ? p : 0.0f;

        // width-16 inclusive product scan -> cumA / chunk A
        float pf = a;
        #pragma unroll
        for (int off = 1; off < CLEN; off <<= 1) {
            float v = __shfl_up_sync(0x0000FFFFu, pf, off, CLEN);
            if (t >= off) pf *= v;
        }
        g_cumA[b * J_ + j] = pf;
        if (t == CLEN - 1) g_partialA[b * NCH + c] = pf;

        // width-8 segmented inclusive product -> per-subgroup correction wts
        float ps = a;
        #pragma unroll
        for (int off = 1; off < SLEN; off <<= 1) {
            float v = __shfl_up_sync(0x0000FFFFu, ps, off, SLEN);
            if ((t & (SLEN - 1)) >= off) ps *= v;
        }
        sSeg[t] = ps;
    }
    __syncthreads();

    // subgroup zero-start scan over its 8 steps (loads batched, MLP=8)
    const int jb = g * SLEN;
    const size_t base = ((size_t)b * J_ + (size_t)c * CLEN + jb) * D4 + d4;
    const float4* ep = emb + base;

    float4 e[SLEN];
    #pragma unroll
    for (int i = 0; i < SLEN; i++) e[i] = __ldcs(ep + (size_t)i * D4);

    float4 prev = make_float4(0.f, 0.f, 0.f, 0.f);
    #pragma unroll
    for (int i = 0; i < SLEN; i++) {
        const float a = sa[jb + i], bb = sb[jb + i];
        prev.x = fmaf(a, prev.x, bb * e[i].x);
        prev.y = fmaf(a, prev.y, bb * e[i].y);
        prev.z = fmaf(a, prev.z, bb * e[i].z);
        prev.w = fmaf(a, prev.w, bb * e[i].w);
        e[i] = prev;                             // e[i] becomes p[i]
    }
    if (g == 0) sEnd[d4] = prev;
    __syncthreads();

    // entering carry for subgroup 1; subgroup 0 enters at zero
    float4 cg = make_float4(0.f, 0.f, 0.f, 0.f);
    if (g == 1) cg = sEnd[d4];

    // corrected values: s[j] = p[j] + seg(j) * cg ; store coalesced
    float4* sp = g_smoothed + base;
    float4 last;
    #pragma unroll
    for (int i = 0; i < SLEN; i++) {
        const float w = sSeg[jb + i];
        float4 r;
        r.x = fmaf(w, cg.x, e[i].x);
        r.y = fmaf(w, cg.y, e[i].y);
        r.z = fmaf(w, cg.z, e[i].z);
        r.w = fmaf(w, cg.w, e[i].w);
        sp[(size_t)i * D4] = r;
        last = r;
    }
    if (g == NSG - 1)
        g_partialEnd[(b * NCH + c) * D4 + d4] = last;
}

// ---------------------------------------------------------------------------
// Kernel 2 (merged): blocks 0..15 -> carry combine (NCH=64, streamed);
//                    blocks 16..31 -> boundary idx scan
// ---------------------------------------------------------------------------
__global__ void k_mid(const int* __restrict__ bnd) {
    if (blockIdx.x < B_) {
        const int b = blockIdx.x, t = threadIdx.x;
        if (t >= D4) return;
        __shared__ float sA[NCH];
        for (int c = t; c < NCH; c += D4) sA[c] = g_partialA[b * NCH + c];
        __syncthreads();

        const float4* __restrict__ ep = g_partialEnd + b * NCH * D4 + t;
        float4* __restrict__ cp = g_carry + b * NCH * D4 + t;

        float4 s = make_float4(0.f, 0.f, 0.f, 0.f);
        cp[0] = s;
        #pragma unroll 16
        for (int c = 1; c < NCH; c++) {
            const float4 e = ep[(c - 1) * D4];
            const float A = sA[c - 1];
            s.x = fmaf(A, s.x, e.x);
            s.y = fmaf(A, s.y, e.y);
            s.z = fmaf(A, s.z, e.z);
            s.w = fmaf(A, s.w, e.w);
            cp[c * D4] = s;
        }
    } else {
        const int b = blockIdx.x - B_, t = threadIdx.x;
        const int lane = t & 31, w = t >> 5;   // 8 warps
        __shared__ int wsum[8];

        const int* p = bnd + b * L_ + t * 16;
        int v[16];
        int s = 0;
        #pragma unroll
        for (int i = 0; i < 16; i++) { v[i] = p[i]; s += (v[i] != 0); }

        int incl = s;
        #pragma unroll
        for (int off = 1; off < 32; off <<= 1) {
            int u = __shfl_up_sync(0xFFFFFFFFu, incl, off);
            if (lane >= off) incl += u;
        }
        if (lane == 31) wsum[w] = incl;
        __syncthreads();
        if (t < 8) {
            int x = wsum[t];
            #pragma unroll
            for (int off = 1; off < 8; off <<= 1) {
                int u = __shfl_up_sync(0x000000FFu, x, off);
                if (t >= off) x += u;
            }
            wsum[t] = x;
        }
        __syncthreads();

        int run = incl - s + (w ? wsum[w - 1] : 0);   // exclusive prefix
        int* op = g_idx + b * L_ + t * 16;
        #pragma unroll
        for (int i = 0; i < 16; i++) {
            run += (v[i] != 0);
            int id = run - 1;
            id = id < 0 ? 0 : (id > (J_ - 1) ? (J_ - 1) : id);
            op[i] = id;
        }
    }
}

// ---------------------------------------------------------------------------
// Kernel 3: fused correction + gather, one warp per (b,l) row.
// out[b,l,d] = smoothed[b,j,d] + cumA[b,j] * carry[b, j/CLEN, d], j = idx[b,l]
// ---------------------------------------------------------------------------
__global__ void k_gather(float4* __restrict__ out) {
    const unsigned int wg = (blockIdx.x * blockDim.x + threadIdx.x) >> 5;
    const int lane = threadIdx.x & 31;
    const int l = wg & (L_ - 1);
    const int b = wg >> 12;

    const int j = g_idx[b * L_ + l];
    const float w = g_cumA[b * J_ + j];
    const int c = j >> 4;                        // j / CLEN
    const float4* __restrict__ sp = g_smoothed + ((size_t)b * J_ + j) * D4;
    const float4* __restrict__ cp = g_carry + (b * NCH + c) * D4;
    float4* __restrict__ op = out + ((size_t)b * L_ + l) * D4;

    float4 pv[4], cv[4];
    #pragma unroll
    for (int k = 0; k < 4; k++) {
        const int d = k * 32 + lane;
        pv[k] = sp[d];
        cv[k] = cp[d];
    }
    #pragma unroll
    for (int k = 0; k < 4; k++) {
        const int d = k * 32 + lane;
        float4 r;
        r.x = fmaf(w, cv[k].x, pv[k].x);
        r.y = fmaf(w, cv[k].y, pv[k].y);
        r.z = fmaf(w, cv[k].z, pv[k].z);
        r.w = fmaf(w, cv[k].w, pv[k].w);
        op[d] = r;
    }
}

// ---------------------------------------------------------------------------
extern "C" void kernel_launch(void* const* d_in, const int* in_sizes, int n_in,
                              void* d_out, int out_size) {
    const float4* emb  = (const float4*)d_in[0];  // (16,1024,512) f32
    const float*  conf = (const float*)d_in[1];   // (16,1024) f32
    const int*    msk  = (const int*)d_in[2];     // (16,1024) bool->int32
    const int*    bnd  = (const int*)d_in[3];     // (16,4096) bool->int32
    float4* out = (float4*)d_out;                 // (16,4096,512) f32

    k_partial<<<dim3(NCH, B_), 256>>>(emb, conf, msk);
    k_mid<<<2 * B_, 256>>>(bnd);
    k_gather<<<(B_ * L_ * 32) / 256, 256>>>(out);
}

// round 8
// speedup vs baseline: 1.3422x; 1.3422x over previous
#include <cuda_runtime.h>

// Fixed shapes
#define B_   16
#define J_   1024
#define L_   4096
#define D_   512
#define D4   128          // D/4 float4 lanes
#define NCH  32           // chunks along J
#define CLEN 32           // J per chunk
#define NSG  4            // subgroups per chunk (inside block)
#define SLEN 8            // J per subgroup
#define EPSV 1e-4f

// Scratch (device globals)
__device__ float  g_partialA[B_ * NCH];          // per-chunk total decay product
__device__ float  g_cumA[B_ * J_];               // within-chunk inclusive prod(a)
__device__ float4 g_partialEnd[B_ * NCH * D4];   // per-chunk end state (prev=0)
__device__ float4 g_carry[B_ * NCH * D4];        // state entering each chunk
__device__ float4 g_smoothed[B_ * J_ * D4];      // chunk-exact scan, 32 MiB
__device__ int    g_idx[B_ * L_];                // gather indices

// ---------------------------------------------------------------------------
// Kernel 1: grid ((NCH+1), B), 512 threads.
//  blocks c<NCH : per-chunk exact EMA from prev=0 (4 subgroups x 8 steps)
//  blocks c==NCH: boundary-mask scan -> gather indices for batch b
// ---------------------------------------------------------------------------
__global__ void __launch_bounds__(512, 2)
k_partial(const float4* __restrict__ emb,
          const float*  __restrict__ conf,
          const int*    __restrict__ mask,
          const int*    __restrict__ bnd) {
    const int c = blockIdx.x, b = blockIdx.y, t = threadIdx.x;

    if (c == NCH) {
        // ---- boundary scan -> gather idx: 512 threads, 8 elems/thread ----
        const int lane = t & 31, w = t >> 5;    // 16 warps
        __shared__ int wsum[16];

        const int* p = bnd + b * L_ + t * 8;
        int v[8];
        int s = 0;
        #pragma unroll
        for (int i = 0; i < 8; i++) { v[i] = p[i]; s += (v[i] != 0); }

        int incl = s;
        #pragma unroll
        for (int off = 1; off < 32; off <<= 1) {
            int u = __shfl_up_sync(0xFFFFFFFFu, incl, off);
            if (lane >= off) incl += u;
        }
        if (lane == 31) wsum[w] = incl;
        __syncthreads();
        if (t < 16) {
            int x = wsum[t];
            #pragma unroll
            for (int off = 1; off < 16; off <<= 1) {
                int u = __shfl_up_sync(0x0000FFFFu, x, off);
                if (t >= off) x += u;
            }
            wsum[t] = x;
        }
        __syncthreads();

        int run = incl - s + (w ? wsum[w - 1] : 0);   // exclusive prefix
        int* op = g_idx + b * L_ + t * 8;
        #pragma unroll
        for (int i = 0; i < 8; i++) {
            run += (v[i] != 0);
            int id = run - 1;
            id = id < 0 ? 0 : (id > (J_ - 1) ? (J_ - 1) : id);
            op[i] = id;
        }
        return;
    }

    // ---- EMA chunk scan ----
    const int g = t >> 7, d4 = t & 127;

    __shared__ float  sa[CLEN], sb[CLEN], sSeg[CLEN], sGA[NSG];
    __shared__ float4 sEnd[NSG][D4];

    if (t < CLEN) {  // warp 0
        const int j = c * CLEN + t;
        float p = conf[b * J_ + j];
        p = fminf(fmaxf(p, EPSV), 1.0f - EPSV);
        const bool m = mask[b * J_ + j] != 0;
        const float a = m ? (1.0f - p) : 1.0f;
        sa[t] = a;
        sb[t] = m ? p : 0.0f;

        // full inclusive product scan (width 32) -> cumA / chunk A
        float pf = a;
        #pragma unroll
        for (int off = 1; off < 32; off <<= 1) {
            float v = __shfl_up_sync(0xFFFFFFFFu, pf, off);
            if (t >= off) pf *= v;
        }
        g_cumA[b * J_ + j] = pf;
        if (t == 31) g_partialA[b * NCH + c] = pf;

        // segmented inclusive product scan (width 8)
        float ps = a;
        #pragma unroll
        for (int off = 1; off < SLEN; off <<= 1) {
            float v = __shfl_up_sync(0xFFFFFFFFu, ps, off, SLEN);
            if ((t & (SLEN - 1)) >= off) ps *= v;
        }
        sSeg[t] = ps;
        if ((t & (SLEN - 1)) == SLEN - 1) sGA[t >> 3] = ps;
    }
    __syncthreads();

    // subgroup zero-start partial scan (loads batched, MLP=8)
    const int jb = g * SLEN;
    const size_t base = ((size_t)b * J_ + (size_t)c * CLEN + jb) * D4 + d4;
    const float4* ep = emb + base;

    float4 e[SLEN];
    #pragma unroll
    for (int i = 0; i < SLEN; i++) e[i] = ep[(size_t)i * D4];

    float4 prev = make_float4(0.f, 0.f, 0.f, 0.f);
    #pragma unroll
    for (int i = 0; i < SLEN; i++) {
        const float a = sa[jb + i], bb = sb[jb + i];
        prev.x = fmaf(a, prev.x, bb * e[i].x);
        prev.y = fmaf(a, prev.y, bb * e[i].y);
        prev.z = fmaf(a, prev.z, bb * e[i].z);
        prev.w = fmaf(a, prev.w, bb * e[i].w);
        e[i] = prev;                              // e[i] = p[i]
    }
    sEnd[g][d4] = prev;
    __syncthreads();

    // entering carry for this subgroup (<=3 FMAs from shared ends)
    float4 cg = make_float4(0.f, 0.f, 0.f, 0.f);
    if (g >= 1) cg = sEnd[0][d4];
    if (g >= 2) {
        const float4 e1 = sEnd[1][d4];
        const float A1 = sGA[1];
        cg.x = fmaf(A1, cg.x, e1.x);
        cg.y = fmaf(A1, cg.y, e1.y);
        cg.z = fmaf(A1, cg.z, e1.z);
        cg.w = fmaf(A1, cg.w, e1.w);
    }
    if (g >= 3) {
        const float4 e2 = sEnd[2][d4];
        const float A2 = sGA[2];
        cg.x = fmaf(A2, cg.x, e2.x);
        cg.y = fmaf(A2, cg.y, e2.y);
        cg.z = fmaf(A2, cg.z, e2.z);
        cg.w = fmaf(A2, cg.w, e2.w);
    }

    // corrected values: s[j] = p[j] + seg(j) * cg ; store coalesced
    float4* sp = g_smoothed + base;
    float4 last;
    #pragma unroll
    for (int i = 0; i < SLEN; i++) {
        const float w = sSeg[jb + i];
        float4 r;
        r.x = fmaf(w, cg.x, e[i].x);
        r.y = fmaf(w, cg.y, e[i].y);
        r.z = fmaf(w, cg.z, e[i].z);
        r.w = fmaf(w, cg.w, e[i].w);
        sp[(size_t)i * D4] = r;
        last = r;
    }
    if (g == NSG - 1)
        g_partialEnd[(b * NCH + c) * D4 + d4] = last;
}

// ---------------------------------------------------------------------------
// Kernel 2: carry combine only. grid (B), 128 threads, register preload.
// ---------------------------------------------------------------------------
__global__ void k_carry() {
    const int b = blockIdx.x, t = threadIdx.x;
    __shared__ float sA[NCH];
    if (t < NCH) sA[t] = g_partialA[b * NCH + t];

    float4 e[NCH];
    #pragma unroll
    for (int c = 0; c < NCH; c++)
        e[c] = g_partialEnd[(b * NCH + c) * D4 + t];
    __syncthreads();

    float4 s = make_float4(0.f, 0.f, 0.f, 0.f);
    g_carry[(b * NCH + 0) * D4 + t] = s;
    #pragma unroll
    for (int c = 1; c < NCH; c++) {
        const float A = sA[c - 1];
        s.x = fmaf(A, s.x, e[c - 1].x);
        s.y = fmaf(A, s.y, e[c - 1].y);
        s.z = fmaf(A, s.z, e[c - 1].z);
        s.w = fmaf(A, s.w, e[c - 1].w);
        g_carry[(b * NCH + c) * D4 + t] = s;
    }
}

// ---------------------------------------------------------------------------
// Kernel 3: fused correction + gather, one warp per (b,l) row.
// out[b,l,d] = smoothed[b,j,d] + cumA[b,j] * carry[b, j>>5, d], j = idx[b,l]
// ---------------------------------------------------------------------------
__global__ void k_gather(float4* __restrict__ out) {
    const unsigned int wg = (blockIdx.x * blockDim.x + threadIdx.x) >> 5;
    const int lane = threadIdx.x & 31;
    const int l = wg & (L_ - 1);
    const int b = wg >> 12;

    const int j = g_idx[b * L_ + l];
    const float w = g_cumA[b * J_ + j];
    const int c = j >> 5;
    const float4* __restrict__ sp = g_smoothed + ((size_t)b * J_ + j) * D4;
    const float4* __restrict__ cp = g_carry + (b * NCH + c) * D4;
    float4* __restrict__ op = out + ((size_t)b * L_ + l) * D4;

    float4 pv[4], cv[4];
    #pragma unroll
    for (int k = 0; k < 4; k++) {
        const int d = k * 32 + lane;
        pv[k] = sp[d];
        cv[k] = cp[d];
    }
    #pragma unroll
    for (int k = 0; k < 4; k++) {
        const int d = k * 32 + lane;
        float4 r;
        r.x = fmaf(w, cv[k].x, pv[k].x);
        r.y = fmaf(w, cv[k].y, pv[k].y);
        r.z = fmaf(w, cv[k].z, pv[k].z);
        r.w = fmaf(w, cv[k].w, pv[k].w);
        op[d] = r;
    }
}

// ---------------------------------------------------------------------------
extern "C" void kernel_launch(void* const* d_in, const int* in_sizes, int n_in,
                              void* d_out, int out_size) {
    const float4* emb  = (const float4*)d_in[0];  // (16,1024,512) f32
    const float*  conf = (const float*)d_in[1];   // (16,1024) f32
    const int*    msk  = (const int*)d_in[2];     // (16,1024) bool->int32
    const int*    bnd  = (const int*)d_in[3];     // (16,4096) bool->int32
    float4* out = (float4*)d_out;                 // (16,4096,512) f32

    k_partial<<<dim3(NCH + 1, B_), 512>>>(emb, conf, msk, bnd);
    k_carry<<<B_, D4>>>();
    k_gather<<<(B_ * L_ * 32) / 256, 256>>>(out);
}

// round 9
// speedup vs baseline: 1.5184x; 1.1313x over previous
#include <cuda_runtime.h>

// Fixed shapes
#define B_   16
#define J_   1024
#define L_   4096
#define D_   512
#define D4   128          // D/4 float4 lanes
#define NCH  32           // chunks along J
#define CLEN 32           // J per chunk
#define NSG  4            // subgroups per chunk (inside block)
#define SLEN 8            // J per subgroup
#define EPSV 1e-4f

// Scratch (device globals)
__device__ float  g_partialA[B_ * NCH];          // per-chunk total decay product
__device__ float  g_cumA[B_ * J_];               // within-chunk inclusive prod(a)
__device__ float4 g_partialEnd[B_ * NCH * D4];   // per-chunk end state (prev=0)
__device__ float4 g_carry[B_ * NCH * D4];        // state entering each chunk
__device__ float4 g_smoothed[B_ * J_ * D4];      // chunk-exact scan, 32 MiB
__device__ int    g_idx[B_ * L_];                // gather indices

// ---------------------------------------------------------------------------
// Kernel 1: grid ((NCH+1), B), 512 threads.
//  blocks c<NCH : per-chunk exact EMA from prev=0 (4 subgroups x 8 steps)
//  blocks c==NCH: boundary-mask scan -> gather indices for batch b
// ---------------------------------------------------------------------------
__global__ void __launch_bounds__(512, 2)
k_partial(const float4* __restrict__ emb,
          const float*  __restrict__ conf,
          const int*    __restrict__ mask,
          const int*    __restrict__ bnd) {
    const int c = blockIdx.x, b = blockIdx.y, t = threadIdx.x;

    if (c == NCH) {
        // ---- boundary scan -> gather idx: 512 threads, 8 elems/thread ----
        const int lane = t & 31, w = t >> 5;    // 16 warps
        __shared__ int wsum[16];

        const int* p = bnd + b * L_ + t * 8;
        int v[8];
        int s = 0;
        #pragma unroll
        for (int i = 0; i < 8; i++) { v[i] = p[i]; s += (v[i] != 0); }

        int incl = s;
        #pragma unroll
        for (int off = 1; off < 32; off <<= 1) {
            int u = __shfl_up_sync(0xFFFFFFFFu, incl, off);
            if (lane >= off) incl += u;
        }
        if (lane == 31) wsum[w] = incl;
        __syncthreads();
        if (t < 16) {
            int x = wsum[t];
            #pragma unroll
            for (int off = 1; off < 16; off <<= 1) {
                int u = __shfl_up_sync(0x0000FFFFu, x, off);
                if (t >= off) x += u;
            }
            wsum[t] = x;
        }
        __syncthreads();

        int run = incl - s + (w ? wsum[w - 1] : 0);   // exclusive prefix
        int* op = g_idx + b * L_ + t * 8;
        #pragma unroll
        for (int i = 0; i < 8; i++) {
            run += (v[i] != 0);
            int id = run - 1;
            id = id < 0 ? 0 : (id > (J_ - 1) ? (J_ - 1) : id);
            op[i] = id;
        }
        return;
    }

    // ---- EMA chunk scan ----
    const int g = t >> 7, d4 = t & 127;

    __shared__ float  sa[CLEN], sb[CLEN], sSeg[CLEN], sGA[NSG];
    __shared__ float4 sEnd[NSG][D4];

    if (t < CLEN) {  // warp 0
        const int j = c * CLEN + t;
        float p = conf[b * J_ + j];
        p = fminf(fmaxf(p, EPSV), 1.0f - EPSV);
        const bool m = mask[b * J_ + j] != 0;
        const float a = m ? (1.0f - p) : 1.0f;
        sa[t] = a;
        sb[t] = m ? p : 0.0f;

        // full inclusive product scan (width 32) -> cumA / chunk A
        float pf = a;
        #pragma unroll
        for (int off = 1; off < 32; off <<= 1) {
            float v = __shfl_up_sync(0xFFFFFFFFu, pf, off);
            if (t >= off) pf *= v;
        }
        g_cumA[b * J_ + j] = pf;
        if (t == 31) g_partialA[b * NCH + c] = pf;

        // segmented inclusive product scan (width 8)
        float ps = a;
        #pragma unroll
        for (int off = 1; off < SLEN; off <<= 1) {
            float v = __shfl_up_sync(0xFFFFFFFFu, ps, off, SLEN);
            if ((t & (SLEN - 1)) >= off) ps *= v;
        }
        sSeg[t] = ps;
        if ((t & (SLEN - 1)) == SLEN - 1) sGA[t >> 3] = ps;
    }
    __syncthreads();

    // subgroup zero-start partial scan (streaming loads, MLP=8)
    const int jb = g * SLEN;
    const size_t base = ((size_t)b * J_ + (size_t)c * CLEN + jb) * D4 + d4;
    const float4* ep = emb + base;

    float4 e[SLEN];
    #pragma unroll
    for (int i = 0; i < SLEN; i++) e[i] = __ldcs(ep + (size_t)i * D4);

    float4 prev = make_float4(0.f, 0.f, 0.f, 0.f);
    #pragma unroll
    for (int i = 0; i < SLEN; i++) {
        const float a = sa[jb + i], bb = sb[jb + i];
        prev.x = fmaf(a, prev.x, bb * e[i].x);
        prev.y = fmaf(a, prev.y, bb * e[i].y);
        prev.z = fmaf(a, prev.z, bb * e[i].z);
        prev.w = fmaf(a, prev.w, bb * e[i].w);
        e[i] = prev;                              // e[i] = p[i]
    }
    sEnd[g][d4] = prev;
    __syncthreads();

    // entering carry for this subgroup (<=3 FMAs from shared ends)
    float4 cg = make_float4(0.f, 0.f, 0.f, 0.f);
    if (g >= 1) cg = sEnd[0][d4];
    if (g >= 2) {
        const float4 e1 = sEnd[1][d4];
        const float A1 = sGA[1];
        cg.x = fmaf(A1, cg.x, e1.x);
        cg.y = fmaf(A1, cg.y, e1.y);
        cg.z = fmaf(A1, cg.z, e1.z);
        cg.w = fmaf(A1, cg.w, e1.w);
    }
    if (g >= 3) {
        const float4 e2 = sEnd[2][d4];
        const float A2 = sGA[2];
        cg.x = fmaf(A2, cg.x, e2.x);
        cg.y = fmaf(A2, cg.y, e2.y);
        cg.z = fmaf(A2, cg.z, e2.z);
        cg.w = fmaf(A2, cg.w, e2.w);
    }

    // corrected values: s[j] = p[j] + seg(j) * cg ; store coalesced
    float4* sp = g_smoothed + base;
    float4 last;
    #pragma unroll
    for (int i = 0; i < SLEN; i++) {
        const float w = sSeg[jb + i];
        float4 r;
        r.x = fmaf(w, cg.x, e[i].x);
        r.y = fmaf(w, cg.y, e[i].y);
        r.z = fmaf(w, cg.z, e[i].z);
        r.w = fmaf(w, cg.w, e[i].w);
        sp[(size_t)i * D4] = r;
        last = r;
    }
    if (g == NSG - 1)
        g_partialEnd[(b * NCH + c) * D4 + d4] = last;
}

// ---------------------------------------------------------------------------
// Kernel 2: carry combine only. grid (B), 128 threads, register preload.
// ---------------------------------------------------------------------------
__global__ void k_carry() {
    const int b = blockIdx.x, t = threadIdx.x;
    __shared__ float sA[NCH];
    if (t < NCH) sA[t] = g_partialA[b * NCH + t];

    float4 e[NCH];
    #pragma unroll
    for (int c = 0; c < NCH; c++)
        e[c] = g_partialEnd[(b * NCH + c) * D4 + t];
    __syncthreads();

    float4 s = make_float4(0.f, 0.f, 0.f, 0.f);
    g_carry[(b * NCH + 0) * D4 + t] = s;
    #pragma unroll
    for (int c = 1; c < NCH; c++) {
        const float A = sA[c - 1];
        s.x = fmaf(A, s.x, e[c - 1].x);
        s.y = fmaf(A, s.y, e[c - 1].y);
        s.z = fmaf(A, s.z, e[c - 1].z);
        s.w = fmaf(A, s.w, e[c - 1].w);
        g_carry[(b * NCH + c) * D4 + t] = s;
    }
}

// ---------------------------------------------------------------------------
// Kernel 3: fused correction + gather, one warp per (b,l) row.
// out[b,l,d] = smoothed[b,j,d] + cumA[b,j] * carry[b, j>>5, d], j = idx[b,l]
// out stores are streaming (__stcs): never re-read, keep L2 for smoothed.
// ---------------------------------------------------------------------------
__global__ void k_gather(float4* __restrict__ out) {
    const unsigned int wg = (blockIdx.x * blockDim.x + threadIdx.x) >> 5;
    const int lane = threadIdx.x & 31;
    const int l = wg & (L_ - 1);
    const int b = wg >> 12;

    const int j = g_idx[b * L_ + l];
    const float w = g_cumA[b * J_ + j];
    const int c = j >> 5;
    const float4* __restrict__ sp = g_smoothed + ((size_t)b * J_ + j) * D4;
    const float4* __restrict__ cp = g_carry + (b * NCH + c) * D4;
    float4* __restrict__ op = out + ((size_t)b * L_ + l) * D4;

    float4 pv[4], cv[4];
    #pragma unroll
    for (int k = 0; k < 4; k++) {
        const int d = k * 32 + lane;
        pv[k] = sp[d];
        cv[k] = cp[d];
    }
    #pragma unroll
    for (int k = 0; k < 4; k++) {
        const int d = k * 32 + lane;
        float4 r;
        r.x = fmaf(w, cv[k].x, pv[k].x);
        r.y = fmaf(w, cv[k].y, pv[k].y);
        r.z = fmaf(w, cv[k].z, pv[k].z);
        r.w = fmaf(w, cv[k].w, pv[k].w);
        __stcs(op + d, r);
    }
}

// ---------------------------------------------------------------------------
extern "C" void kernel_launch(void* const* d_in, const int* in_sizes, int n_in,
                              void* d_out, int out_size) {
    const float4* emb  = (const float4*)d_in[0];  // (16,1024,512) f32
    const float*  conf = (const float*)d_in[1];   // (16,1024) f32
    const int*    msk  = (const int*)d_in[2];     // (16,1024) bool->int32
    const int*    bnd  = (const int*)d_in[3];     // (16,4096) bool->int32
    float4* out = (float4*)d_out;                 // (16,4096,512) f32

    k_partial<<<dim3(NCH + 1, B_), 512>>>(emb, conf, msk, bnd);
    k_carry<<<B_, D4>>>();
    k_gather<<<(B_ * L_ * 32) / 256, 256>>>(out);
}

// round 10
// speedup vs baseline: 1.5337x; 1.0101x over previous
#include <cuda_runtime.h>

// Fixed shapes
#define B_   16
#define J_   1024
#define L_   4096
#define D_   512
#define D4   128          // D/4 float4 lanes
#define NCH  32           // chunks along J
#define CLEN 32           // J per chunk
#define NSG  4            // subgroups per chunk (inside block)
#define SLEN 8            // J per subgroup
#define EPSV 1e-4f

// Scratch (device globals)
__device__ float  g_partialA[B_ * NCH];          // per-chunk total decay product
__device__ float  g_cumA[B_ * J_];               // within-chunk inclusive prod(a)
__device__ float4 g_partialEnd[B_ * NCH * D4];   // per-chunk end state (prev=0)
__device__ float4 g_carry[B_ * NCH * D4];        // state entering each chunk
__device__ float4 g_smoothed[B_ * J_ * D4];      // chunk-exact scan, 32 MiB
__device__ int    g_idx[B_ * L_];                // gather indices

// ---------------------------------------------------------------------------
// Kernel 1: grid ((NCH+1), B), 512 threads.
//  blocks c<NCH : per-chunk exact EMA from prev=0 (4 subgroups x 8 steps)
//  blocks c==NCH: boundary-mask scan -> gather indices for batch b
// Main emb loads are issued BEFORE the warp-0 prologue so the prologue's
// DRAM latency + shuffle pyramids hide under the in-flight loads.
// ---------------------------------------------------------------------------
__global__ void __launch_bounds__(512, 2)
k_partial(const float4* __restrict__ emb,
          const float*  __restrict__ conf,
          const int*    __restrict__ mask,
          const int*    __restrict__ bnd) {
    const int c = blockIdx.x, b = blockIdx.y, t = threadIdx.x;

    if (c == NCH) {
        // ---- boundary scan -> gather idx: 512 threads, 8 elems/thread ----
        const int lane = t & 31, w = t >> 5;    // 16 warps
        __shared__ int wsum[16];

        const int* p = bnd + b * L_ + t * 8;
        int v[8];
        int s = 0;
        #pragma unroll
        for (int i = 0; i < 8; i++) { v[i] = p[i]; s += (v[i] != 0); }

        int incl = s;
        #pragma unroll
        for (int off = 1; off < 32; off <<= 1) {
            int u = __shfl_up_sync(0xFFFFFFFFu, incl, off);
            if (lane >= off) incl += u;
        }
        if (lane == 31) wsum[w] = incl;
        __syncthreads();
        if (t < 16) {
            int x = wsum[t];
            #pragma unroll
            for (int off = 1; off < 16; off <<= 1) {
                int u = __shfl_up_sync(0x0000FFFFu, x, off);
                if (t >= off) x += u;
            }
            wsum[t] = x;
        }
        __syncthreads();

        int run = incl - s + (w ? wsum[w - 1] : 0);   // exclusive prefix
        int* op = g_idx + b * L_ + t * 8;
        #pragma unroll
        for (int i = 0; i < 8; i++) {
            run += (v[i] != 0);
            int id = run - 1;
            id = id < 0 ? 0 : (id > (J_ - 1) ? (J_ - 1) : id);
            op[i] = id;
        }
        return;
    }

    // ---- EMA chunk scan ----
    const int g = t >> 7, d4 = t & 127;

    __shared__ float  sa[CLEN], sb[CLEN], sSeg[CLEN], sGA[NSG];
    __shared__ float4 sEnd[NSG][D4];

    // 1) issue the main loads FIRST (independent of everything below)
    const int jb = g * SLEN;
    const size_t base = ((size_t)b * J_ + (size_t)c * CLEN + jb) * D4 + d4;
    const float4* ep = emb + base;

    float4 e[SLEN];
    #pragma unroll
    for (int i = 0; i < SLEN; i++) e[i] = __ldcs(ep + (size_t)i * D4);

    // 2) warp-0 prologue runs while the loads are in flight
    if (t < CLEN) {
        const int j = c * CLEN + t;
        float p = conf[b * J_ + j];
        p = fminf(fmaxf(p, EPSV), 1.0f - EPSV);
        const bool m = mask[b * J_ + j] != 0;
        const float a = m ? (1.0f - p) : 1.0f;
        sa[t] = a;
        sb[t] = m ? p : 0.0f;

        // full inclusive product scan (width 32) -> cumA / chunk A
        float pf = a;
        #pragma unroll
        for (int off = 1; off < 32; off <<= 1) {
            float v = __shfl_up_sync(0xFFFFFFFFu, pf, off);
            if (t >= off) pf *= v;
        }
        g_cumA[b * J_ + j] = pf;
        if (t == 31) g_partialA[b * NCH + c] = pf;

        // segmented inclusive product scan (width 8)
        float ps = a;
        #pragma unroll
        for (int off = 1; off < SLEN; off <<= 1) {
            float v = __shfl_up_sync(0xFFFFFFFFu, ps, off, SLEN);
            if ((t & (SLEN - 1)) >= off) ps *= v;
        }
        sSeg[t] = ps;
        if ((t & (SLEN - 1)) == SLEN - 1) sGA[t >> 3] = ps;
    }
    __syncthreads();

    // 3) subgroup zero-start partial scan consuming the prefetched e[]
    float4 prev = make_float4(0.f, 0.f, 0.f, 0.f);
    #pragma unroll
    for (int i = 0; i < SLEN; i++) {
        const float a = sa[jb + i], bb = sb[jb + i];
        prev.x = fmaf(a, prev.x, bb * e[i].x);
        prev.y = fmaf(a, prev.y, bb * e[i].y);
        prev.z = fmaf(a, prev.z, bb * e[i].z);
        prev.w = fmaf(a, prev.w, bb * e[i].w);
        e[i] = prev;                              // e[i] = p[i]
    }
    sEnd[g][d4] = prev;
    __syncthreads();

    // entering carry for this subgroup (<=3 FMAs from shared ends)
    float4 cg = make_float4(0.f, 0.f, 0.f, 0.f);
    if (g >= 1) cg = sEnd[0][d4];
    if (g >= 2) {
        const float4 e1 = sEnd[1][d4];
        const float A1 = sGA[1];
        cg.x = fmaf(A1, cg.x, e1.x);
        cg.y = fmaf(A1, cg.y, e1.y);
        cg.z = fmaf(A1, cg.z, e1.z);
        cg.w = fmaf(A1, cg.w, e1.w);
    }
    if (g >= 3) {
        const float4 e2 = sEnd[2][d4];
        const float A2 = sGA[2];
        cg.x = fmaf(A2, cg.x, e2.x);
        cg.y = fmaf(A2, cg.y, e2.y);
        cg.z = fmaf(A2, cg.z, e2.z);
        cg.w = fmaf(A2, cg.w, e2.w);
    }

    // corrected values: s[j] = p[j] + seg(j) * cg ; store coalesced
    float4* sp = g_smoothed + base;
    float4 last;
    #pragma unroll
    for (int i = 0; i < SLEN; i++) {
        const float w = sSeg[jb + i];
        float4 r;
        r.x = fmaf(w, cg.x, e[i].x);
        r.y = fmaf(w, cg.y, e[i].y);
        r.z = fmaf(w, cg.z, e[i].z);
        r.w = fmaf(w, cg.w, e[i].w);
        sp[(size_t)i * D4] = r;
        last = r;
    }
    if (g == NSG - 1)
        g_partialEnd[(b * NCH + c) * D4 + d4] = last;
}

// ---------------------------------------------------------------------------
// Kernel 2: carry combine only. grid (B), 128 threads, register preload.
// ---------------------------------------------------------------------------
__global__ void k_carry() {
    const int b = blockIdx.x, t = threadIdx.x;
    __shared__ float sA[NCH];
    if (t < NCH) sA[t] = g_partialA[b * NCH + t];

    float4 e[NCH];
    #pragma unroll
    for (int c = 0; c < NCH; c++)
        e[c] = g_partialEnd[(b * NCH + c) * D4 + t];
    __syncthreads();

    float4 s = make_float4(0.f, 0.f, 0.f, 0.f);
    g_carry[(b * NCH + 0) * D4 + t] = s;
    #pragma unroll
    for (int c = 1; c < NCH; c++) {
        const float A = sA[c - 1];
        s.x = fmaf(A, s.x, e[c - 1].x);
        s.y = fmaf(A, s.y, e[c - 1].y);
        s.z = fmaf(A, s.z, e[c - 1].z);
        s.w = fmaf(A, s.w, e[c - 1].w);
        g_carry[(b * NCH + c) * D4 + t] = s;
    }
}

// ---------------------------------------------------------------------------
// Kernel 3: fused correction + gather, one warp per (b,l) row.
// out[b,l,d] = smoothed[b,j,d] + cumA[b,j] * carry[b, j>>5, d], j = idx[b,l]
// out stores are streaming (__stcs): never re-read, keep L2 for smoothed.
// ---------------------------------------------------------------------------
__global__ void k_gather(float4* __restrict__ out) {
    const unsigned int wg = (blockIdx.x * blockDim.x + threadIdx.x) >> 5;
    const int lane = threadIdx.x & 31;
    const int l = wg & (L_ - 1);
    const int b = wg >> 12;

    const int j = g_idx[b * L_ + l];
    const float w = g_cumA[b * J_ + j];
    const int c = j >> 5;
    const float4* __restrict__ sp = g_smoothed + ((size_t)b * J_ + j) * D4;
    const float4* __restrict__ cp = g_carry + (b * NCH + c) * D4;
    float4* __restrict__ op = out + ((size_t)b * L_ + l) * D4;

    float4 pv[4], cv[4];
    #pragma unroll
    for (int k = 0; k < 4; k++) {
        const int d = k * 32 + lane;
        pv[k] = sp[d];
        cv[k] = cp[d];
    }
    #pragma unroll
    for (int k = 0; k < 4; k++) {
        const int d = k * 32 + lane;
        float4 r;
        r.x = fmaf(w, cv[k].x, pv[k].x);
        r.y = fmaf(w, cv[k].y, pv[k].y);
        r.z = fmaf(w, cv[k].z, pv[k].z);
        r.w = fmaf(w, cv[k].w, pv[k].w);
        __stcs(op + d, r);
    }
}

// ---------------------------------------------------------------------------
extern "C" void kernel_launch(void* const* d_in, const int* in_sizes, int n_in,
                              void* d_out, int out_size) {
    const float4* emb  = (const float4*)d_in[0];  // (16,1024,512) f32
    const float*  conf = (const float*)d_in[1];   // (16,1024) f32
    const int*    msk  = (const int*)d_in[2];     // (16,1024) bool->int32
    const int*    bnd  = (const int*)d_in[3];     // (16,4096) bool->int32
    float4* out = (float4*)d_out;                 // (16,4096,512) f32

    k_partial<<<dim3(NCH + 1, B_), 512>>>(emb, conf, msk, bnd);
    k_carry<<<B_, D4>>>();
    k_gather<<<(B_ * L_ * 32) / 256, 256>>>(out);
}